// round 14
// baseline (speedup 1.0000x reference)
#include <cuda_runtime.h>
#include <cuda_bf16.h>
#include <stdint.h>

// out[src[e]*16 + k] += attr_flat[k*E + e]
// Round-13: round-12 PDL structure + separately-compiled guard-free scatter
// selected when E % TILE == 0 (true here: 4,000,000 = 15625*256).

#define TILE 256

__global__ __launch_bounds__(1024) void zero_out_kernel(float4* __restrict__ out,
                                                        int n4) {
    // Trigger at entry: dependent scatter grid may launch now; its
    // cudaGridDependencySynchronize() still waits for our completion+flush.
    cudaTriggerProgrammaticLaunchCompletion();
    for (int i = blockIdx.x * blockDim.x + threadIdx.x; i < n4;
         i += gridDim.x * blockDim.x)
        out[i] = make_float4(0.f, 0.f, 0.f, 0.f);
}

// ---- Guard-free fast path: requires E % TILE == 0 ----
__global__ __launch_bounds__(TILE) void scatter_f16_full_kernel(
        const float* __restrict__ attr,
        const int* __restrict__ src_idx,
        float* __restrict__ out,
        int E) {
    __shared__ float vals[TILE][20];   // edge-major, 80B rows (16B-aligned)
    __shared__ int   sidx[TILE];

    const int t = threadIdx.x;
    const int base = blockIdx.x * TILE;
    const int e = base + t;

    // Preamble (independent of out): coalesced feature-major loads + transpose
    sidx[t] = src_idx[e];
    float v[16];
#pragma unroll
    for (int k = 0; k < 16; k++)
        v[k] = attr[(size_t)k * E + e];
#pragma unroll
    for (int kg = 0; kg < 4; kg++) {
        float4 p = make_float4(v[4*kg+0], v[4*kg+1], v[4*kg+2], v[4*kg+3]);
        *reinterpret_cast<float4*>(&vals[t][4*kg]) = p;
    }
    __syncthreads();

    // Wait for zero_out completion (zeros visible in L2)
    cudaGridDependencySynchronize();

    // Scatter: lane l -> edge (l/4), feature-group (l%4); 4 consecutive lanes
    // cover one contiguous 64B output row -> merged RED wavefronts.
    const int kg = t & 3;
    const int eg = t >> 2;           // 0..63
#pragma unroll
    for (int q = 0; q < 4; q++) {
        const int el = eg + 64 * q;  // 0..255
        const int s = sidx[el];                          // 4-lane broadcast
        float4 p = *reinterpret_cast<const float4*>(&vals[el][4*kg]);
        float* dst = out + (size_t)s * 16 + 4 * kg;      // 16B-aligned
        asm volatile("red.global.add.v4.f32 [%0], {%1, %2, %3, %4};"
                     :: "l"(dst), "f"(p.x), "f"(p.y), "f"(p.z), "f"(p.w)
                     : "memory");
    }
}

// ---- Guarded variant (any E) ----
__global__ __launch_bounds__(TILE) void scatter_f16_kernel(
        const float* __restrict__ attr,
        const int* __restrict__ src_idx,
        float* __restrict__ out,
        int E) {
    __shared__ float vals[TILE][20];
    __shared__ int   sidx[TILE];

    const int t = threadIdx.x;
    const int base = blockIdx.x * TILE;
    const int e = base + t;

    if (e < E) {
        sidx[t] = src_idx[e];
        float v[16];
#pragma unroll
        for (int k = 0; k < 16; k++)
            v[k] = attr[(size_t)k * E + e];
#pragma unroll
        for (int kg = 0; kg < 4; kg++) {
            float4 p = make_float4(v[4*kg+0], v[4*kg+1], v[4*kg+2], v[4*kg+3]);
            *reinterpret_cast<float4*>(&vals[t][4*kg]) = p;
        }
    }
    __syncthreads();

    cudaGridDependencySynchronize();

    const int kg = t & 3;
    const int eg = t >> 2;
#pragma unroll
    for (int q = 0; q < 4; q++) {
        const int el = eg + 64 * q;
        if (base + el < E) {
            const int s = sidx[el];
            float4 p = *reinterpret_cast<const float4*>(&vals[el][4*kg]);
            float* dst = out + (size_t)s * 16 + 4 * kg;
            asm volatile("red.global.add.v4.f32 [%0], {%1, %2, %3, %4};"
                         :: "l"(dst), "f"(p.x), "f"(p.y), "f"(p.z), "f"(p.w)
                         : "memory");
        }
    }
}

// Generic fallback for F != 16 (plain serialized two-kernel path).
__global__ void zero_out_plain(float4* __restrict__ out, int n4) {
    for (int i = blockIdx.x * blockDim.x + threadIdx.x; i < n4;
         i += gridDim.x * blockDim.x)
        out[i] = make_float4(0.f, 0.f, 0.f, 0.f);
}
__global__ void scatter_generic_kernel(const float* __restrict__ attr,
                                       const int* __restrict__ src_idx,
                                       float* __restrict__ out,
                                       int E, int F) {
    int e = blockIdx.x * blockDim.x + threadIdx.x;
    if (e >= E) return;
    const int s = src_idx[e];
    for (int k = 0; k < F; k++)
        atomicAdd(&out[(size_t)s * F + k], attr[(size_t)k * E + e]);
}

extern "C" void kernel_launch(void* const* d_in, const int* in_sizes, int n_in,
                              void* d_out, int out_size) {
    const float* attr = (const float*)d_in[0];   // (E, F) float32, flat
    const int*   idx  = (const int*)d_in[1];     // (2, E) int32; row 0 = src

    const int E = in_sizes[1] / 2;
    const int F = in_sizes[0] / E;
    float* out = (float*)d_out;

    if (F == 16) {
        int n4 = out_size / 4;
        int zblocks = (n4 + 1023) / 1024;
        if (zblocks > 64) zblocks = 64;          // hidden under PDL anyway
        zero_out_kernel<<<zblocks, 1024>>>((float4*)out, n4);

        int blocks = (E + TILE - 1) / TILE;
        cudaLaunchConfig_t cfg = {};
        cfg.gridDim = dim3((unsigned)blocks, 1, 1);
        cfg.blockDim = dim3(TILE, 1, 1);
        cfg.dynamicSmemBytes = 0;
        cfg.stream = 0;                          // same (captured) stream
        cudaLaunchAttribute attrs[1];
        attrs[0].id = cudaLaunchAttributeProgrammaticStreamSerialization;
        attrs[0].val.programmaticStreamSerializationAllowed = 1;
        cfg.attrs = attrs;
        cfg.numAttrs = 1;
        if (E % TILE == 0)
            cudaLaunchKernelEx(&cfg, scatter_f16_full_kernel, attr, idx, out, E);
        else
            cudaLaunchKernelEx(&cfg, scatter_f16_kernel, attr, idx, out, E);
    } else {
        int n4 = out_size / 4;
        int zblocks = (n4 + 1023) / 1024;
        if (zblocks > 148) zblocks = 148;
        zero_out_plain<<<zblocks, 1024>>>((float4*)out, n4);
        int blocks = (E + 255) / 256;
        scatter_generic_kernel<<<blocks, 256>>>(attr, idx, out, E, F);
    }
}

// round 15
// speedup vs baseline: 1.1594x; 1.1594x over previous
#include <cuda_runtime.h>
#include <cuda_bf16.h>
#include <stdint.h>

// out[src[e]*16 + k] += attr_flat[k*E + e]
// FINAL (= round-12, best measured 64.0us): guarded scatter (the predicates
// are load-bearing for ptxas's high-MLP schedule — removing them regressed
// 11us in round 13) + PDL with entry trigger so the zero kernel and launch
// gap hide under the scatter's LDG/transpose preamble.

#define TILE 256

__global__ __launch_bounds__(1024) void zero_out_kernel(float4* __restrict__ out,
                                                        int n4) {
    // Fire first: dependent grid may start launching now. Correctness is
    // carried by the consumer's cudaGridDependencySynchronize(), which waits
    // for this grid's completion + memory flush regardless of trigger timing.
    cudaTriggerProgrammaticLaunchCompletion();
    for (int i = blockIdx.x * blockDim.x + threadIdx.x; i < n4;
         i += gridDim.x * blockDim.x)
        out[i] = make_float4(0.f, 0.f, 0.f, 0.f);
}

__global__ __launch_bounds__(TILE) void scatter_f16_kernel(
        const float* __restrict__ attr,
        const int* __restrict__ src_idx,
        float* __restrict__ out,
        int E) {
    // Edge-major staging: row stride 20 floats (80B, 16B-aligned).
    __shared__ float vals[TILE][20];
    __shared__ int   sidx[TILE];

    const int t = threadIdx.x;
    const int base = blockIdx.x * TILE;
    const int e = base + t;

    // ---- Preamble (independent of out): coalesced loads + transpose ----
    if (e < E) {
        sidx[t] = src_idx[e];
        float v[16];
#pragma unroll
        for (int k = 0; k < 16; k++)
            v[k] = attr[(size_t)k * E + e];
#pragma unroll
        for (int kg = 0; kg < 4; kg++) {
            float4 p = make_float4(v[4*kg+0], v[4*kg+1], v[4*kg+2], v[4*kg+3]);
            *reinterpret_cast<float4*>(&vals[t][4*kg]) = p;
        }
    }
    __syncthreads();

    // ---- Wait for zero_out_kernel completion (zeros visible in L2) ----
    cudaGridDependencySynchronize();

    // ---- Scatter: lane l -> edge (l/4), feature-group (l%4) ----
    // 4 consecutive lanes cover one contiguous 64B output row -> the warp's
    // RED.v4 merges into ~8 wavefronts instead of 32.
    const int kg = t & 3;
    const int eg = t >> 2;           // 0..63
#pragma unroll
    for (int q = 0; q < 4; q++) {
        const int el = eg + 64 * q;  // 0..255
        if (base + el < E) {
            const int s = sidx[el];                          // 4-lane broadcast
            float4 p = *reinterpret_cast<const float4*>(&vals[el][4*kg]);
            float* dst = out + (size_t)s * 16 + 4 * kg;      // 16B-aligned
            asm volatile("red.global.add.v4.f32 [%0], {%1, %2, %3, %4};"
                         :: "l"(dst), "f"(p.x), "f"(p.y), "f"(p.z), "f"(p.w)
                         : "memory");
        }
    }
}

// Generic fallback for F != 16 (plain serialized two-kernel path).
__global__ void zero_out_plain(float4* __restrict__ out, int n4) {
    for (int i = blockIdx.x * blockDim.x + threadIdx.x; i < n4;
         i += gridDim.x * blockDim.x)
        out[i] = make_float4(0.f, 0.f, 0.f, 0.f);
}
__global__ void scatter_generic_kernel(const float* __restrict__ attr,
                                       const int* __restrict__ src_idx,
                                       float* __restrict__ out,
                                       int E, int F) {
    int e = blockIdx.x * blockDim.x + threadIdx.x;
    if (e >= E) return;
    const int s = src_idx[e];
    for (int k = 0; k < F; k++)
        atomicAdd(&out[(size_t)s * F + k], attr[(size_t)k * E + e]);
}

extern "C" void kernel_launch(void* const* d_in, const int* in_sizes, int n_in,
                              void* d_out, int out_size) {
    const float* attr = (const float*)d_in[0];   // (E, F) float32, flat
    const int*   idx  = (const int*)d_in[1];     // (2, E) int32; row 0 = src

    const int E = in_sizes[1] / 2;
    const int F = in_sizes[0] / E;
    float* out = (float*)d_out;

    if (F == 16) {
        int n4 = out_size / 4;
        int zblocks = (n4 + 1023) / 1024;
        if (zblocks > 148) zblocks = 148;        // one wave, grid-stride
        zero_out_kernel<<<zblocks, 1024>>>((float4*)out, n4);

        int blocks = (E + TILE - 1) / TILE;
        cudaLaunchConfig_t cfg = {};
        cfg.gridDim = dim3((unsigned)blocks, 1, 1);
        cfg.blockDim = dim3(TILE, 1, 1);
        cfg.dynamicSmemBytes = 0;
        cfg.stream = 0;                          // same (captured) stream
        cudaLaunchAttribute attrs[1];
        attrs[0].id = cudaLaunchAttributeProgrammaticStreamSerialization;
        attrs[0].val.programmaticStreamSerializationAllowed = 1;
        cfg.attrs = attrs;
        cfg.numAttrs = 1;
        cudaLaunchKernelEx(&cfg, scatter_f16_kernel, attr, idx, out, E);
    } else {
        int n4 = out_size / 4;
        int zblocks = (n4 + 1023) / 1024;
        if (zblocks > 148) zblocks = 148;
        zero_out_plain<<<zblocks, 1024>>>((float4*)out, n4);
        int blocks = (E + 255) / 256;
        scatter_generic_kernel<<<blocks, 256>>>(attr, idx, out, E, F);
    }
}

// round 16
// speedup vs baseline: 1.1640x; 1.0040x over previous
#include <cuda_runtime.h>
#include <cuda_bf16.h>
#include <stdint.h>

// out[src[e]*16 + k] += attr_flat[k*E + e]
// FINAL (best measured 64.0us; re-confirmed 64.26us): guarded scatter (the
// predicates are load-bearing for ptxas's high-MLP schedule — removing them
// regressed 11us) + PDL with entry trigger so the zero kernel and launch gap
// hide under the scatter's LDG/transpose preamble.

#define TILE 256

__global__ __launch_bounds__(1024) void zero_out_kernel(float4* __restrict__ out,
                                                        int n4) {
    // Fire first: dependent grid may start launching now. Correctness is
    // carried by the consumer's cudaGridDependencySynchronize(), which waits
    // for this grid's completion + memory flush regardless of trigger timing.
    cudaTriggerProgrammaticLaunchCompletion();
    for (int i = blockIdx.x * blockDim.x + threadIdx.x; i < n4;
         i += gridDim.x * blockDim.x)
        out[i] = make_float4(0.f, 0.f, 0.f, 0.f);
}

__global__ __launch_bounds__(TILE) void scatter_f16_kernel(
        const float* __restrict__ attr,
        const int* __restrict__ src_idx,
        float* __restrict__ out,
        int E) {
    // Edge-major staging: row stride 20 floats (80B, 16B-aligned).
    __shared__ float vals[TILE][20];
    __shared__ int   sidx[TILE];

    const int t = threadIdx.x;
    const int base = blockIdx.x * TILE;
    const int e = base + t;

    // ---- Preamble (independent of out): coalesced loads + transpose ----
    if (e < E) {
        sidx[t] = src_idx[e];
        float v[16];
#pragma unroll
        for (int k = 0; k < 16; k++)
            v[k] = attr[(size_t)k * E + e];
#pragma unroll
        for (int kg = 0; kg < 4; kg++) {
            float4 p = make_float4(v[4*kg+0], v[4*kg+1], v[4*kg+2], v[4*kg+3]);
            *reinterpret_cast<float4*>(&vals[t][4*kg]) = p;
        }
    }
    __syncthreads();

    // ---- Wait for zero_out_kernel completion (zeros visible in L2) ----
    cudaGridDependencySynchronize();

    // ---- Scatter: lane l -> edge (l/4), feature-group (l%4) ----
    // 4 consecutive lanes cover one contiguous 64B output row -> the warp's
    // RED.v4 merges into ~8 wavefronts instead of 32.
    const int kg = t & 3;
    const int eg = t >> 2;           // 0..63
#pragma unroll
    for (int q = 0; q < 4; q++) {
        const int el = eg + 64 * q;  // 0..255
        if (base + el < E) {
            const int s = sidx[el];                          // 4-lane broadcast
            float4 p = *reinterpret_cast<const float4*>(&vals[el][4*kg]);
            float* dst = out + (size_t)s * 16 + 4 * kg;      // 16B-aligned
            asm volatile("red.global.add.v4.f32 [%0], {%1, %2, %3, %4};"
                         :: "l"(dst), "f"(p.x), "f"(p.y), "f"(p.z), "f"(p.w)
                         : "memory");
        }
    }
}

// Generic fallback for F != 16 (plain serialized two-kernel path).
__global__ void zero_out_plain(float4* __restrict__ out, int n4) {
    for (int i = blockIdx.x * blockDim.x + threadIdx.x; i < n4;
         i += gridDim.x * blockDim.x)
        out[i] = make_float4(0.f, 0.f, 0.f, 0.f);
}
__global__ void scatter_generic_kernel(const float* __restrict__ attr,
                                       const int* __restrict__ src_idx,
                                       float* __restrict__ out,
                                       int E, int F) {
    int e = blockIdx.x * blockDim.x + threadIdx.x;
    if (e >= E) return;
    const int s = src_idx[e];
    for (int k = 0; k < F; k++)
        atomicAdd(&out[(size_t)s * F + k], attr[(size_t)k * E + e]);
}

extern "C" void kernel_launch(void* const* d_in, const int* in_sizes, int n_in,
                              void* d_out, int out_size) {
    const float* attr = (const float*)d_in[0];   // (E, F) float32, flat
    const int*   idx  = (const int*)d_in[1];     // (2, E) int32; row 0 = src

    const int E = in_sizes[1] / 2;
    const int F = in_sizes[0] / E;
    float* out = (float*)d_out;

    if (F == 16) {
        int n4 = out_size / 4;
        int zblocks = (n4 + 1023) / 1024;
        if (zblocks > 148) zblocks = 148;        // one wave, grid-stride
        zero_out_kernel<<<zblocks, 1024>>>((float4*)out, n4);

        int blocks = (E + TILE - 1) / TILE;
        cudaLaunchConfig_t cfg = {};
        cfg.gridDim = dim3((unsigned)blocks, 1, 1);
        cfg.blockDim = dim3(TILE, 1, 1);
        cfg.dynamicSmemBytes = 0;
        cfg.stream = 0;                          // same (captured) stream
        cudaLaunchAttribute attrs[1];
        attrs[0].id = cudaLaunchAttributeProgrammaticStreamSerialization;
        attrs[0].val.programmaticStreamSerializationAllowed = 1;
        cfg.attrs = attrs;
        cfg.numAttrs = 1;
        cudaLaunchKernelEx(&cfg, scatter_f16_kernel, attr, idx, out, E);
    } else {
        int n4 = out_size / 4;
        int zblocks = (n4 + 1023) / 1024;
        if (zblocks > 148) zblocks = 148;
        zero_out_plain<<<zblocks, 1024>>>((float4*)out, n4);
        int blocks = (E + 255) / 256;
        scatter_generic_kernel<<<blocks, 256>>>(attr, idx, out, E, F);
    }
}